// round 3
// baseline (speedup 1.0000x reference)
#include <cuda_runtime.h>
#include <cuda_bf16.h>
#include <math.h>

// ---------------- problem-size constants (fixed per dataset) ----------------
#define NMAX 100000
#define EMAX 3200000
#define F_IN 512
#define F_MID 16
#define F_OUT 64

// ---------------- scratch (static device allocations; no cudaMalloc) -------
__device__ int   g_is64;               // edge_index dtype flag (1 = int64)
__device__ int   g_cnt[NMAX];          // in-degree (excl self loop)
__device__ float g_dinv[NMAX];         // rsqrt(deg+1)
__device__ int   g_incl[NMAX];         // tile-inclusive scan temp
__device__ int   g_tilesums[128];
__device__ int   g_tileoff[128];
__device__ int   g_rowptr[NMAX + 1];
__device__ int   g_cursor[NMAX];
__device__ int   g_col[EMAX];          // CSR source indices grouped by dst
__device__ __align__(16) float g_hp[NMAX * F_MID];    // (x@W1)*dinv
__device__ __align__(16) float g_h1p[NMAX * F_MID];   // relu(layer1)*dinv
__device__ __align__(16) float g_agg2[NMAX * F_MID];  // dinv * sum(h1p)

// ---------------- dtype detection -------------------------------------------
// JAX default config demotes int64 -> int32; detect which layout we actually
// got. If the buffer really is int64, the first 16 values (as int64) are all
// valid node ids in [0, N). If it is int32 data misread as int64, each read
// combines two random ids (lo + hi*2^32) and the test fails almost surely.
__global__ void k_detect(const long long* __restrict__ ei) {
    if (threadIdx.x == 0 && blockIdx.x == 0) {
        bool ok64 = true;
        #pragma unroll
        for (int i = 0; i < 16; i++) {
            long long v = ei[i];
            if (v < 0 || v >= NMAX) ok64 = false;
        }
        g_is64 = ok64 ? 1 : 0;
    }
}

__device__ __forceinline__ int edge_at(const void* ei, long long idx) {
    if (g_is64) return (int)((const long long*)ei)[idx];
    return ((const int*)ei)[idx];
}

// ---------------- degree count ----------------------------------------------
__global__ void k_init(int n) {
    int i = blockIdx.x * blockDim.x + threadIdx.x;
    if (i < n) g_cnt[i] = 0;
}

__global__ void k_count(const void* __restrict__ ei, int E) {
    int e = blockIdx.x * blockDim.x + threadIdx.x;
    if (e < E) {
        int d = edge_at(ei, (long long)E + e);  // dst row
        if (d >= 0 && d < NMAX) atomicAdd(&g_cnt[d], 1);
    }
}

// ---------------- 3-kernel exclusive scan (N ~ 100K, tile = 1024) -----------
__global__ void k_scan1(int n) {
    __shared__ int s[1024];
    int idx = blockIdx.x * 1024 + threadIdx.x;
    int v = (idx < n) ? g_cnt[idx] : 0;
    if (idx < n) g_dinv[idx] = rsqrtf((float)(v + 1));  // +1 self loop
    s[threadIdx.x] = v;
    __syncthreads();
    #pragma unroll
    for (int d = 1; d < 1024; d <<= 1) {
        int t = (threadIdx.x >= d) ? s[threadIdx.x - d] : 0;
        __syncthreads();
        s[threadIdx.x] += t;
        __syncthreads();
    }
    if (idx < n) g_incl[idx] = s[threadIdx.x];
    if (threadIdx.x == 1023) g_tilesums[blockIdx.x] = s[1023];
}

__global__ void k_scan2(int tiles) {
    __shared__ int s[128];
    int t = threadIdx.x;
    int v = (t < tiles) ? g_tilesums[t] : 0;
    s[t] = v;
    __syncthreads();
    #pragma unroll
    for (int d = 1; d < 128; d <<= 1) {
        int u = (t >= d) ? s[t - d] : 0;
        __syncthreads();
        s[t] += u;
        __syncthreads();
    }
    g_tileoff[t] = s[t] - v;  // exclusive prefix of tile sums
}

__global__ void k_scan3(int n) {
    int i = blockIdx.x * blockDim.x + threadIdx.x;
    if (i > n) return;
    int val = (i == 0) ? 0 : (g_incl[i - 1] + g_tileoff[(i - 1) >> 10]);
    g_rowptr[i] = val;
    if (i < n) g_cursor[i] = val;
}

// ---------------- CSR bucket fill -------------------------------------------
__global__ void k_fill(const void* __restrict__ ei, int E) {
    int e = blockIdx.x * blockDim.x + threadIdx.x;
    if (e < E) {
        int s = edge_at(ei, e);
        int d = edge_at(ei, (long long)E + e);
        if (s >= 0 && s < NMAX && d >= 0 && d < NMAX) {
            int pos = atomicAdd(&g_cursor[d], 1);
            g_col[pos] = s;
        }
    }
}

// ---------------- GEMM1: hp = (x @ W1) * dinv[row]  (100000x512 @ 512x16) ---
__global__ __launch_bounds__(256) void k_gemm1(const float* __restrict__ x,
                                               const float* __restrict__ W1,
                                               int n) {
    __shared__ float Xs[128][33];                 // padded: conflict-free
    __shared__ __align__(16) float Ws[32][16];    // K-chunk of W1
    const int tid = threadIdx.x;
    const int row0 = blockIdx.x * 128;
    const int r = tid >> 1;        // 0..127 row within tile
    const int h = tid & 1;         // output half: 8 features each
    float acc[8] = {0.f, 0.f, 0.f, 0.f, 0.f, 0.f, 0.f, 0.f};

    for (int k0 = 0; k0 < F_IN; k0 += 32) {
        // stage X tile: 128 rows x 32 k, coalesced
        #pragma unroll
        for (int i = 0; i < 16; i++) {
            int lin = tid + 256 * i;
            int rr = lin >> 5, cc = lin & 31;
            int grow = row0 + rr;
            Xs[rr][cc] = (grow < n) ? x[(long long)grow * F_IN + k0 + cc] : 0.f;
        }
        // stage W chunk: 32x16 = 512 floats
        ((float*)Ws)[tid]       = W1[k0 * F_MID + tid];
        ((float*)Ws)[tid + 256] = W1[k0 * F_MID + tid + 256];
        __syncthreads();

        #pragma unroll
        for (int kk = 0; kk < 32; kk++) {
            float xv = Xs[r][kk];
            float4 w0 = *reinterpret_cast<const float4*>(&Ws[kk][h * 8]);
            float4 w1 = *reinterpret_cast<const float4*>(&Ws[kk][h * 8 + 4]);
            acc[0] = fmaf(xv, w0.x, acc[0]);
            acc[1] = fmaf(xv, w0.y, acc[1]);
            acc[2] = fmaf(xv, w0.z, acc[2]);
            acc[3] = fmaf(xv, w0.w, acc[3]);
            acc[4] = fmaf(xv, w1.x, acc[4]);
            acc[5] = fmaf(xv, w1.y, acc[5]);
            acc[6] = fmaf(xv, w1.z, acc[6]);
            acc[7] = fmaf(xv, w1.w, acc[7]);
        }
        __syncthreads();
    }

    int grow = row0 + r;
    if (grow < n) {
        float dv = g_dinv[grow];
        float4 o0 = make_float4(acc[0] * dv, acc[1] * dv, acc[2] * dv, acc[3] * dv);
        float4 o1 = make_float4(acc[4] * dv, acc[5] * dv, acc[6] * dv, acc[7] * dv);
        float4* dst = reinterpret_cast<float4*>(&g_hp[(long long)grow * F_MID + h * 8]);
        dst[0] = o0;
        dst[1] = o1;
    }
}

// ---------------- aggregation: warp per node, 8 edges x float4 per step -----
// MODE 1: h1p = relu(dinv*S + b1) * dinv    (hp -> h1p)
// MODE 2: agg2 = dinv*S                     (h1p -> agg2)
template <int MODE>
__global__ __launch_bounds__(256) void k_agg(const float* __restrict__ bias, int n) {
    const int warp = (blockIdx.x * blockDim.x + threadIdx.x) >> 5;
    const int lane = threadIdx.x & 31;
    if (warp >= n) return;
    const int v = warp;
    const int g = lane >> 2;   // edge slot 0..7
    const int c = lane & 3;    // float4 index within 16 features

    const float* __restrict__ msg = (MODE == 1) ? g_hp : g_h1p;
    float* __restrict__ outp      = (MODE == 1) ? g_h1p : g_agg2;

    const int base = g_rowptr[v];
    const int end  = g_rowptr[v + 1];

    float4 acc = make_float4(0.f, 0.f, 0.f, 0.f);
    for (int i = base + g; i < end; i += 8) {
        int s = __ldg(&g_col[i]);
        float4 m = *reinterpret_cast<const float4*>(&msg[(long long)s * F_MID + c * 4]);
        acc.x += m.x; acc.y += m.y; acc.z += m.z; acc.w += m.w;
    }
    // reduce over the 8 edge slots (xor 4, 8, 16)
    #pragma unroll
    for (int d = 4; d < 32; d <<= 1) {
        acc.x += __shfl_xor_sync(0xffffffffu, acc.x, d);
        acc.y += __shfl_xor_sync(0xffffffffu, acc.y, d);
        acc.z += __shfl_xor_sync(0xffffffffu, acc.z, d);
        acc.w += __shfl_xor_sync(0xffffffffu, acc.w, d);
    }
    if (lane < 4) {
        float4 self = *reinterpret_cast<const float4*>(&msg[(long long)v * F_MID + lane * 4]);
        acc.x += self.x; acc.y += self.y; acc.z += self.z; acc.w += self.w;
        float dv = g_dinv[v];
        float4 o;
        if (MODE == 1) {
            float4 bb = *reinterpret_cast<const float4*>(&bias[lane * 4]);
            o.x = fmaxf(acc.x * dv + bb.x, 0.f) * dv;
            o.y = fmaxf(acc.y * dv + bb.y, 0.f) * dv;
            o.z = fmaxf(acc.z * dv + bb.z, 0.f) * dv;
            o.w = fmaxf(acc.w * dv + bb.w, 0.f) * dv;
        } else {
            o.x = acc.x * dv; o.y = acc.y * dv; o.z = acc.z * dv; o.w = acc.w * dv;
        }
        *reinterpret_cast<float4*>(&outp[(long long)v * F_MID + lane * 4]) = o;
    }
}

// ---------------- output GEMM (16->64) + b2 + log_softmax -------------------
__global__ __launch_bounds__(256) void k_out(const float* __restrict__ W2,
                                             const float* __restrict__ b2,
                                             float* __restrict__ out, int n) {
    __shared__ float W2s[F_MID * F_OUT];  // 1024 floats
    int tid = threadIdx.x;
    for (int i = tid; i < F_MID * F_OUT; i += 256) W2s[i] = W2[i];
    __syncthreads();

    const int warp = (blockIdx.x * 256 + tid) >> 5;
    const int lane = tid & 31;
    if (warp >= n) return;

    const float* __restrict__ s2 = &g_agg2[(long long)warp * F_MID];
    float a = b2[lane];
    float b = b2[lane + 32];
    #pragma unroll
    for (int f = 0; f < F_MID; f++) {
        float sv = s2[f];  // warp-uniform broadcast
        a = fmaf(sv, W2s[f * F_OUT + lane], a);
        b = fmaf(sv, W2s[f * F_OUT + lane + 32], b);
    }
    float M = fmaxf(a, b);
    #pragma unroll
    for (int d = 16; d > 0; d >>= 1) M = fmaxf(M, __shfl_xor_sync(0xffffffffu, M, d));
    float sum = expf(a - M) + expf(b - M);
    #pragma unroll
    for (int d = 16; d > 0; d >>= 1) sum += __shfl_xor_sync(0xffffffffu, sum, d);
    float lz = M + logf(sum);
    out[(long long)warp * F_OUT + lane]      = a - lz;
    out[(long long)warp * F_OUT + lane + 32] = b - lz;
}

// ---------------- launch ----------------------------------------------------
extern "C" void kernel_launch(void* const* d_in, const int* in_sizes, int n_in,
                              void* d_out, int out_size) {
    const float* x  = (const float*)d_in[0];
    const void*  ei = d_in[1];
    const float* W1 = (const float*)d_in[2];
    const float* b1 = (const float*)d_in[3];
    const float* W2 = (const float*)d_in[4];
    const float* b2 = (const float*)d_in[5];
    float*       out = (float*)d_out;

    const int n = in_sizes[0] / F_IN;          // 100000
    const int E = in_sizes[1] / 2;             // 3200000

    const int B = 256;
    const int nodeGrid  = (n + B - 1) / B;
    const int edgeGrid  = (E + B - 1) / B;
    const int tiles     = (n + 1023) / 1024;
    const int warpGrid  = (n + 7) / 8;         // 8 warps per 256-thread block

    k_detect<<<1, 32>>>((const long long*)ei);
    k_init<<<nodeGrid, B>>>(n);
    k_count<<<edgeGrid, B>>>(ei, E);
    k_scan1<<<tiles, 1024>>>(n);
    k_scan2<<<1, 128>>>(tiles);
    k_scan3<<<(n + 1 + B - 1) / B, B>>>(n);
    k_fill<<<edgeGrid, B>>>(ei, E);
    k_gemm1<<<(n + 127) / 128, B>>>(x, W1, n);
    k_agg<1><<<warpGrid, B>>>(b1, n);
    k_agg<2><<<warpGrid, B>>>(nullptr, n);
    k_out<<<warpGrid, B>>>(W2, b2, out, n);
}

// round 7
// speedup vs baseline: 1.1112x; 1.1112x over previous
#include <cuda_runtime.h>
#include <cuda_bf16.h>
#include <math.h>

// ---------------- problem-size constants (fixed per dataset) ----------------
#define NMAX 100000
#define EMAX 3200000
#define F_IN 512
#define F_MID 16
#define F_OUT 64

// ---------------- scratch (static device allocations; no cudaMalloc) -------
__device__ int   g_is64;               // edge_index dtype flag (1 = int64)
__device__ int   g_cnt[NMAX];          // in-degree (excl self loop)
__device__ float g_dinv[NMAX];         // rsqrt(deg+1)
__device__ int   g_incl[NMAX];         // tile-inclusive scan temp
__device__ int   g_tilesums[128];
__device__ int   g_tileoff[128];
__device__ int   g_rowptr[NMAX + 1];
__device__ int   g_cursor[NMAX];
__device__ int   g_col[EMAX];          // CSR source indices grouped by dst
__device__ __align__(16) float g_hp[NMAX * F_MID];    // (x@W1)*dinv
__device__ __align__(16) float g_h1p[NMAX * F_MID];   // relu(layer1)*dinv

// ---------------- init + dtype detection -------------------------------------
// JAX default config demotes int64 -> int32; detect which layout we actually
// got: if the first 16 int64 reads are all valid node ids, it's real int64.
__global__ void k_init_detect(const long long* __restrict__ ei, int n) {
    int i = blockIdx.x * blockDim.x + threadIdx.x;
    if (i < n) g_cnt[i] = 0;
    if (i == 0) {
        bool ok64 = true;
        #pragma unroll
        for (int t = 0; t < 16; t++) {
            long long v = ei[t];
            if (v < 0 || v >= NMAX) ok64 = false;
        }
        g_is64 = ok64 ? 1 : 0;
    }
}

__device__ __forceinline__ int edge_at(const void* ei, long long idx) {
    if (g_is64) return (int)((const long long*)ei)[idx];
    return ((const int*)ei)[idx];
}

// ---------------- degree count ----------------------------------------------
__global__ void k_count(const void* __restrict__ ei, int E) {
    int e = blockIdx.x * blockDim.x + threadIdx.x;
    if (e < E) {
        int d = edge_at(ei, (long long)E + e);  // dst row
        if (d >= 0 && d < NMAX) atomicAdd(&g_cnt[d], 1);
    }
}

// ---------------- scan: warp-shuffle version (tile = 1024) ------------------
__global__ void k_scan1(int n) {
    __shared__ int wsum[32];
    const int lane = threadIdx.x & 31;
    const int wid = threadIdx.x >> 5;
    int idx = blockIdx.x * 1024 + threadIdx.x;
    int v = (idx < n) ? g_cnt[idx] : 0;
    if (idx < n) g_dinv[idx] = rsqrtf((float)(v + 1));  // +1 self loop

    int s = v;
    #pragma unroll
    for (int d = 1; d < 32; d <<= 1) {
        int t = __shfl_up_sync(0xffffffffu, s, d);
        if (lane >= d) s += t;
    }
    if (lane == 31) wsum[wid] = s;
    __syncthreads();
    if (wid == 0) {
        int w = wsum[lane];
        #pragma unroll
        for (int d = 1; d < 32; d <<= 1) {
            int t = __shfl_up_sync(0xffffffffu, w, d);
            if (lane >= d) w += t;
        }
        wsum[lane] = w;  // inclusive over warp sums
    }
    __syncthreads();
    if (wid > 0) s += wsum[wid - 1];
    if (idx < n) g_incl[idx] = s;
    if (threadIdx.x == 1023) g_tilesums[blockIdx.x] = s;
}

__global__ void k_scan2(int tiles) {
    __shared__ int s[128];
    int t = threadIdx.x;
    int v = (t < tiles) ? g_tilesums[t] : 0;
    s[t] = v;
    __syncthreads();
    #pragma unroll
    for (int d = 1; d < 128; d <<= 1) {
        int u = (t >= d) ? s[t - d] : 0;
        __syncthreads();
        s[t] += u;
        __syncthreads();
    }
    g_tileoff[t] = s[t] - v;  // exclusive prefix of tile sums
}

__global__ void k_scan3(int n) {
    int i = blockIdx.x * blockDim.x + threadIdx.x;
    if (i > n) return;
    int val = (i == 0) ? 0 : (g_incl[i - 1] + g_tileoff[(i - 1) >> 10]);
    g_rowptr[i] = val;
    if (i < n) g_cursor[i] = val;
}

// ---------------- CSR bucket fill -------------------------------------------
__global__ void k_fill(const void* __restrict__ ei, int E) {
    int e = blockIdx.x * blockDim.x + threadIdx.x;
    if (e < E) {
        int s = edge_at(ei, e);
        int d = edge_at(ei, (long long)E + e);
        if (s >= 0 && s < NMAX && d >= 0 && d < NMAX) {
            int pos = atomicAdd(&g_cursor[d], 1);
            g_col[pos] = s;
        }
    }
}

// ---------------- GEMM1: hp = (x @ W1) * dinv[row]  (100000x512 @ 512x16) ---
// f32x2 packed-FMA version: each thread owns 1 row x 8 features held as four
// packed (f, f+1) accumulators. Weights are loaded directly into u64 pairs
// with ld.shared.v2.b64 (no pack cost); x is duplicated once per k.
__global__ __launch_bounds__(256) void k_gemm1(const float* __restrict__ x,
                                               const float* __restrict__ W1,
                                               int n) {
    __shared__ float Xs[128][33];                 // +1 pad: conflict-free
    __shared__ __align__(16) float Ws[32][16];    // K-chunk of W1
    const int tid = threadIdx.x;
    const int row0 = blockIdx.x * 128;
    const int r = tid >> 1;        // 0..127 row within tile
    const int h = tid & 1;         // output half: 8 features each

    unsigned long long acc0 = 0ull, acc1 = 0ull, acc2 = 0ull, acc3 = 0ull;

    unsigned int ws_base =
        (unsigned int)__cvta_generic_to_shared(&Ws[0][0]) + (unsigned int)(h * 32);

    for (int k0 = 0; k0 < F_IN; k0 += 32) {
        // stage X tile: 128 rows x 32 k, float4 loads (4 per thread)
        #pragma unroll
        for (int j = 0; j < 4; j++) {
            int lin = tid + 256 * j;           // 0..1023
            int rr = lin >> 3;                  // 0..127
            int cc = (lin & 7) << 2;            // 0,4,...,28
            int grow = row0 + rr;
            float4 v = make_float4(0.f, 0.f, 0.f, 0.f);
            if (grow < n)
                v = *reinterpret_cast<const float4*>(&x[(long long)grow * F_IN + k0 + cc]);
            Xs[rr][cc + 0] = v.x;
            Xs[rr][cc + 1] = v.y;
            Xs[rr][cc + 2] = v.z;
            Xs[rr][cc + 3] = v.w;
        }
        // stage W chunk: 32x16 = 512 floats
        ((float*)Ws)[tid]       = W1[k0 * F_MID + tid];
        ((float*)Ws)[tid + 256] = W1[k0 * F_MID + tid + 256];
        __syncthreads();

        #pragma unroll
        for (int kk = 0; kk < 32; kk++) {
            float xv = Xs[r][kk];
            unsigned long long xx;
            asm("mov.b64 %0, {%1, %1};" : "=l"(xx) : "f"(xv));
            unsigned long long w01, w23, w45, w67;
            unsigned int a0 = ws_base + (unsigned int)(kk * 64);
            asm("ld.shared.v2.b64 {%0, %1}, [%2];"
                : "=l"(w01), "=l"(w23) : "r"(a0));
            asm("ld.shared.v2.b64 {%0, %1}, [%2];"
                : "=l"(w45), "=l"(w67) : "r"(a0 + 16));
            asm("fma.rn.f32x2 %0, %1, %2, %0;" : "+l"(acc0) : "l"(xx), "l"(w01));
            asm("fma.rn.f32x2 %0, %1, %2, %0;" : "+l"(acc1) : "l"(xx), "l"(w23));
            asm("fma.rn.f32x2 %0, %1, %2, %0;" : "+l"(acc2) : "l"(xx), "l"(w45));
            asm("fma.rn.f32x2 %0, %1, %2, %0;" : "+l"(acc3) : "l"(xx), "l"(w67));
        }
        __syncthreads();
    }

    int grow = row0 + r;
    if (grow < n) {
        float dv = g_dinv[grow];
        float f0, f1, f2, f3, f4, f5, f6, f7;
        asm("mov.b64 {%0, %1}, %2;" : "=f"(f0), "=f"(f1) : "l"(acc0));
        asm("mov.b64 {%0, %1}, %2;" : "=f"(f2), "=f"(f3) : "l"(acc1));
        asm("mov.b64 {%0, %1}, %2;" : "=f"(f4), "=f"(f5) : "l"(acc2));
        asm("mov.b64 {%0, %1}, %2;" : "=f"(f6), "=f"(f7) : "l"(acc3));
        float4 o0 = make_float4(f0 * dv, f1 * dv, f2 * dv, f3 * dv);
        float4 o1 = make_float4(f4 * dv, f5 * dv, f6 * dv, f7 * dv);
        float4* dst = reinterpret_cast<float4*>(&g_hp[(long long)grow * F_MID + h * 8]);
        dst[0] = o0;
        dst[1] = o1;
    }
}

// ---------------- layer-1 aggregation: warp per node ------------------------
// h1p = relu(dinv*S + b1) * dinv    (hp -> h1p)
__global__ __launch_bounds__(256) void k_agg1(const float* __restrict__ bias, int n) {
    const int warp = (blockIdx.x * blockDim.x + threadIdx.x) >> 5;
    const int lane = threadIdx.x & 31;
    if (warp >= n) return;
    const int v = warp;
    const int g = lane >> 2;   // edge slot 0..7
    const int c = lane & 3;    // float4 index within 16 features

    const int base = g_rowptr[v];
    const int end  = g_rowptr[v + 1];

    float4 acc = make_float4(0.f, 0.f, 0.f, 0.f);
    for (int i = base + g; i < end; i += 8) {
        int s = __ldg(&g_col[i]);
        float4 m = *reinterpret_cast<const float4*>(&g_hp[(long long)s * F_MID + c * 4]);
        acc.x += m.x; acc.y += m.y; acc.z += m.z; acc.w += m.w;
    }
    #pragma unroll
    for (int d = 4; d < 32; d <<= 1) {
        acc.x += __shfl_xor_sync(0xffffffffu, acc.x, d);
        acc.y += __shfl_xor_sync(0xffffffffu, acc.y, d);
        acc.z += __shfl_xor_sync(0xffffffffu, acc.z, d);
        acc.w += __shfl_xor_sync(0xffffffffu, acc.w, d);
    }
    if (lane < 4) {
        float4 self = *reinterpret_cast<const float4*>(&g_hp[(long long)v * F_MID + lane * 4]);
        acc.x += self.x; acc.y += self.y; acc.z += self.z; acc.w += self.w;
        float dv = g_dinv[v];
        float4 bb = *reinterpret_cast<const float4*>(&bias[lane * 4]);
        float4 o;
        o.x = fmaxf(acc.x * dv + bb.x, 0.f) * dv;
        o.y = fmaxf(acc.y * dv + bb.y, 0.f) * dv;
        o.z = fmaxf(acc.z * dv + bb.z, 0.f) * dv;
        o.w = fmaxf(acc.w * dv + bb.w, 0.f) * dv;
        *reinterpret_cast<float4*>(&g_h1p[(long long)v * F_MID + lane * 4]) = o;
    }
}

// ---------------- layer-2 aggregation FUSED with output GEMM + log_softmax --
// s2 = dinv * (sum_{src} h1p[src] + h1p[v]); out = log_softmax(s2 @ W2 + b2)
__global__ __launch_bounds__(256) void k_agg2_out(const float* __restrict__ W2,
                                                 const float* __restrict__ b2,
                                                 float* __restrict__ out, int n) {
    __shared__ float W2s[F_MID * F_OUT];  // 1024 floats
    {
        int tid = threadIdx.x;
        for (int i = tid; i < F_MID * F_OUT; i += 256) W2s[i] = W2[i];
    }
    __syncthreads();

    const int warp = (blockIdx.x * blockDim.x + threadIdx.x) >> 5;
    const int lane = threadIdx.x & 31;
    if (warp >= n) return;
    const int v = warp;
    const int g = lane >> 2;
    const int c = lane & 3;

    const int base = g_rowptr[v];
    const int end  = g_rowptr[v + 1];

    float4 acc = make_float4(0.f, 0.f, 0.f, 0.f);
    for (int i = base + g; i < end; i += 8) {
        int s = __ldg(&g_col[i]);
        float4 m = *reinterpret_cast<const float4*>(&g_h1p[(long long)s * F_MID + c * 4]);
        acc.x += m.x; acc.y += m.y; acc.z += m.z; acc.w += m.w;
    }
    #pragma unroll
    for (int d = 4; d < 32; d <<= 1) {
        acc.x += __shfl_xor_sync(0xffffffffu, acc.x, d);
        acc.y += __shfl_xor_sync(0xffffffffu, acc.y, d);
        acc.z += __shfl_xor_sync(0xffffffffu, acc.z, d);
        acc.w += __shfl_xor_sync(0xffffffffu, acc.w, d);
    }
    if (lane < 4) {  // finalize s2 in lanes 0..3 (lane j holds feats 4j..4j+3)
        float4 self = *reinterpret_cast<const float4*>(&g_h1p[(long long)v * F_MID + lane * 4]);
        float dv = g_dinv[v];
        acc.x = (acc.x + self.x) * dv;
        acc.y = (acc.y + self.y) * dv;
        acc.z = (acc.z + self.z) * dv;
        acc.w = (acc.w + self.w) * dv;
    }
    // broadcast the 16 s2 values to all lanes
    float s2[F_MID];
    #pragma unroll
    for (int j = 0; j < 4; j++) {
        s2[4 * j + 0] = __shfl_sync(0xffffffffu, acc.x, j);
        s2[4 * j + 1] = __shfl_sync(0xffffffffu, acc.y, j);
        s2[4 * j + 2] = __shfl_sync(0xffffffffu, acc.z, j);
        s2[4 * j + 3] = __shfl_sync(0xffffffffu, acc.w, j);
    }
    // output GEMM: each lane computes feats (lane) and (lane+32)
    float a = b2[lane];
    float b = b2[lane + 32];
    #pragma unroll
    for (int f = 0; f < F_MID; f++) {
        a = fmaf(s2[f], W2s[f * F_OUT + lane], a);
        b = fmaf(s2[f], W2s[f * F_OUT + lane + 32], b);
    }
    float M = fmaxf(a, b);
    #pragma unroll
    for (int d = 16; d > 0; d >>= 1) M = fmaxf(M, __shfl_xor_sync(0xffffffffu, M, d));
    float sum = expf(a - M) + expf(b - M);
    #pragma unroll
    for (int d = 16; d > 0; d >>= 1) sum += __shfl_xor_sync(0xffffffffu, sum, d);
    float lz = M + logf(sum);
    out[(long long)v * F_OUT + lane]      = a - lz;
    out[(long long)v * F_OUT + lane + 32] = b - lz;
}

// ---------------- launch ----------------------------------------------------
extern "C" void kernel_launch(void* const* d_in, const int* in_sizes, int n_in,
                              void* d_out, int out_size) {
    const float* x  = (const float*)d_in[0];
    const void*  ei = d_in[1];
    const float* W1 = (const float*)d_in[2];
    const float* b1 = (const float*)d_in[3];
    const float* W2 = (const float*)d_in[4];
    const float* b2 = (const float*)d_in[5];
    float*       out = (float*)d_out;

    const int n = in_sizes[0] / F_IN;          // 100000
    const int E = in_sizes[1] / 2;             // 3200000

    const int B = 256;
    const int nodeGrid  = (n + B - 1) / B;
    const int edgeGrid  = (E + B - 1) / B;
    const int tiles     = (n + 1023) / 1024;
    const int warpGrid  = (n + 7) / 8;         // 8 warps per 256-thread block

    k_init_detect<<<nodeGrid, B>>>((const long long*)ei, n);
    k_count<<<edgeGrid, B>>>(ei, E);
    k_scan1<<<tiles, 1024>>>(n);
    k_scan2<<<1, 128>>>(tiles);
    k_scan3<<<(n + 1 + B - 1) / B, B>>>(n);
    k_gemm1<<<(n + 127) / 128, B>>>(x, W1, n);   // launch #6: ncu -s 5 captures this
    k_fill<<<edgeGrid, B>>>(ei, E);
    k_agg1<<<warpGrid, B>>>(b1, n);
    k_agg2_out<<<warpGrid, B>>>(W2, b2, out, n);
}

// round 8
// speedup vs baseline: 1.1543x; 1.0388x over previous
#include <cuda_runtime.h>
#include <cuda_bf16.h>
#include <math.h>

// ---------------- problem-size constants (fixed per dataset) ----------------
#define NMAX 100000
#define EMAX 3200000
#define F_IN 512
#define F_MID 16
#define F_OUT 64

// ---------------- scratch (static device allocations; no cudaMalloc) -------
__device__ int   g_is64;               // edge_index dtype flag (1 = int64)
__device__ int   g_cnt[NMAX];          // in-degree (excl self loop)
__device__ float g_dinv[NMAX];         // rsqrt(deg+1)
__device__ int   g_tile_pub[128];      // lookback: tile aggregate + 1 (0 = not ready)
__device__ int   g_rowptr[NMAX + 1];
__device__ int   g_cursor[NMAX];
__device__ int   g_col[EMAX];          // CSR source indices grouped by dst
__device__ __align__(16) float g_hp[NMAX * F_MID];    // (x@W1)*dinv
__device__ __align__(16) float g_h1p[NMAX * F_MID];   // relu(layer1)*dinv

// ---------------- init + dtype detection -------------------------------------
// JAX default config demotes int64 -> int32; detect which layout we actually
// got: if the first 16 int64 reads are all valid node ids, it's real int64.
__global__ void k_init_detect(const long long* __restrict__ ei, int n) {
    int i = blockIdx.x * blockDim.x + threadIdx.x;
    if (i < n) g_cnt[i] = 0;
    if (i < 128) g_tile_pub[i] = 0;
    if (i == 0) {
        bool ok64 = true;
        #pragma unroll
        for (int t = 0; t < 16; t++) {
            long long v = ei[t];
            if (v < 0 || v >= NMAX) ok64 = false;
        }
        g_is64 = ok64 ? 1 : 0;
    }
}

// ---------------- degree count (2 edges / thread) ---------------------------
__global__ void k_count(const void* __restrict__ ei, int E) {
    int e2 = (blockIdx.x * blockDim.x + threadIdx.x) * 2;
    if (e2 >= E) return;
    int d0, d1 = -1;
    if (g_is64) {
        const long long* p = (const long long*)ei + (long long)E + e2;
        if (e2 + 1 < E) { longlong2 v = *(const longlong2*)p; d0 = (int)v.x; d1 = (int)v.y; }
        else d0 = (int)p[0];
    } else {
        const int* p = (const int*)ei + E + e2;
        if (e2 + 1 < E) { int2 v = *(const int2*)p; d0 = v.x; d1 = v.y; }
        else d0 = p[0];
    }
    if ((unsigned)d0 < NMAX) atomicAdd(&g_cnt[d0], 1);
    if ((unsigned)d1 < NMAX) atomicAdd(&g_cnt[d1], 1);
}

// ---------------- single-pass scan with decoupled lookback ------------------
// Builds g_rowptr, g_cursor, g_dinv in one launch. 98 tiles of 1024 all fit in
// wave 1 (<=148 SMs), so spinning on lower-indexed tiles cannot deadlock.
// Publication uses a single word (total+1), so no fence is needed.
__global__ void k_scanAll(int n) {
    __shared__ int wsum[32];
    __shared__ int sprefix;
    const int lane = threadIdx.x & 31;
    const int wid  = threadIdx.x >> 5;
    const int b    = blockIdx.x;
    int idx = b * 1024 + threadIdx.x;
    int v = (idx < n) ? g_cnt[idx] : 0;
    if (idx < n) g_dinv[idx] = rsqrtf((float)(v + 1));  // +1 self loop

    int s = v;
    #pragma unroll
    for (int d = 1; d < 32; d <<= 1) {
        int t = __shfl_up_sync(0xffffffffu, s, d);
        if (lane >= d) s += t;
    }
    if (lane == 31) wsum[wid] = s;
    __syncthreads();
    if (wid == 0) {
        int w = wsum[lane];
        #pragma unroll
        for (int d = 1; d < 32; d <<= 1) {
            int t = __shfl_up_sync(0xffffffffu, w, d);
            if (lane >= d) w += t;
        }
        wsum[lane] = w;  // inclusive over warp sums
    }
    __syncthreads();
    if (wid > 0) s += wsum[wid - 1];
    // s = inclusive prefix within tile; tile total = wsum[31]

    if (threadIdx.x == 0) {
        ((volatile int*)g_tile_pub)[b] = wsum[31] + 1;  // publish aggregate
    }
    // lookback: warp 0 sums aggregates of tiles 0..b-1
    if (wid == 0) {
        int pre = 0;
        for (int j = lane; j < b; j += 32) {
            int p;
            do { p = ((volatile int*)g_tile_pub)[j]; } while (p == 0);
            pre += p - 1;
        }
        #pragma unroll
        for (int d = 16; d > 0; d >>= 1)
            pre += __shfl_xor_sync(0xffffffffu, pre, d);
        if (lane == 0) sprefix = pre;
    }
    __syncthreads();
    int excl = sprefix + s - v;
    if (idx < n) {
        g_rowptr[idx] = excl;
        g_cursor[idx] = excl;
        if (idx == n - 1) g_rowptr[n] = sprefix + s;
    }
}

// ---------------- CSR bucket fill (2 edges / thread) -------------------------
__global__ void k_fill(const void* __restrict__ ei, int E) {
    int e2 = (blockIdx.x * blockDim.x + threadIdx.x) * 2;
    if (e2 >= E) return;
    int s0, s1 = -1, d0, d1 = -1;
    if (g_is64) {
        const long long* ps = (const long long*)ei + e2;
        const long long* pd = (const long long*)ei + (long long)E + e2;
        if (e2 + 1 < E) {
            longlong2 vs = *(const longlong2*)ps;
            longlong2 vd = *(const longlong2*)pd;
            s0 = (int)vs.x; s1 = (int)vs.y; d0 = (int)vd.x; d1 = (int)vd.y;
        } else { s0 = (int)ps[0]; d0 = (int)pd[0]; }
    } else {
        const int* ps = (const int*)ei + e2;
        const int* pd = (const int*)ei + E + e2;
        if (e2 + 1 < E) {
            int2 vs = *(const int2*)ps;
            int2 vd = *(const int2*)pd;
            s0 = vs.x; s1 = vs.y; d0 = vd.x; d1 = vd.y;
        } else { s0 = ps[0]; d0 = pd[0]; }
    }
    if ((unsigned)s0 < NMAX && (unsigned)d0 < NMAX) {
        int pos = atomicAdd(&g_cursor[d0], 1);
        g_col[pos] = s0;
    }
    if ((unsigned)s1 < NMAX && (unsigned)d1 < NMAX) {
        int pos = atomicAdd(&g_cursor[d1], 1);
        g_col[pos] = s1;
    }
}

// ---------------- GEMM1: hp = (x @ W1) * dinv[row]  (100000x512 @ 512x16) ---
// f32x2 packed FMAs; W1 staged into smem ONCE (32KB); Xs rows padded to 36
// floats (144B = 16B-aligned) so staging uses STS.128.
__global__ __launch_bounds__(256) void k_gemm1(const float* __restrict__ x,
                                               const float* __restrict__ W1,
                                               int n) {
    __shared__ __align__(16) float Xs[128][36];   // pad 36: STS.128-able
    __shared__ __align__(16) float Ws[F_IN][16];  // full W1: 32KB
    const int tid = threadIdx.x;
    const int row0 = blockIdx.x * 128;
    const int r = tid >> 1;        // 0..127 row within tile
    const int h = tid & 1;         // output half: 8 features each

    // stage W once: 8192 floats = 2048 float4, 8 per thread
    #pragma unroll
    for (int j = 0; j < 8; j++) {
        int idx = tid + 256 * j;
        reinterpret_cast<float4*>(Ws)[idx] = reinterpret_cast<const float4*>(W1)[idx];
    }

    unsigned long long acc0 = 0ull, acc1 = 0ull, acc2 = 0ull, acc3 = 0ull;
    unsigned int ws_base =
        (unsigned int)__cvta_generic_to_shared(&Ws[0][0]) + (unsigned int)(h * 32);

    for (int k0 = 0; k0 < F_IN; k0 += 32) {
        // stage X tile: 128 rows x 32 k, 4x LDG.128 -> 4x STS.128 per thread
        #pragma unroll
        for (int j = 0; j < 4; j++) {
            int lin = tid + 256 * j;            // 0..1023
            int rr = lin >> 3;                  // 0..127
            int cc = (lin & 7) << 2;            // 0,4,...,28
            int grow = row0 + rr;
            float4 v = make_float4(0.f, 0.f, 0.f, 0.f);
            if (grow < n)
                v = *reinterpret_cast<const float4*>(&x[(long long)grow * F_IN + k0 + cc]);
            *reinterpret_cast<float4*>(&Xs[rr][cc]) = v;
        }
        __syncthreads();   // also covers the one-time Ws staging on iter 0

        #pragma unroll
        for (int kk = 0; kk < 32; kk++) {
            float xv = Xs[r][kk];
            unsigned long long xx;
            asm("mov.b64 %0, {%1, %1};" : "=l"(xx) : "f"(xv));
            unsigned long long w01, w23, w45, w67;
            unsigned int a0 = ws_base + (unsigned int)((k0 + kk) * 64);
            asm("ld.shared.v2.b64 {%0, %1}, [%2];"
                : "=l"(w01), "=l"(w23) : "r"(a0));
            asm("ld.shared.v2.b64 {%0, %1}, [%2];"
                : "=l"(w45), "=l"(w67) : "r"(a0 + 16));
            asm("fma.rn.f32x2 %0, %1, %2, %0;" : "+l"(acc0) : "l"(xx), "l"(w01));
            asm("fma.rn.f32x2 %0, %1, %2, %0;" : "+l"(acc1) : "l"(xx), "l"(w23));
            asm("fma.rn.f32x2 %0, %1, %2, %0;" : "+l"(acc2) : "l"(xx), "l"(w45));
            asm("fma.rn.f32x2 %0, %1, %2, %0;" : "+l"(acc3) : "l"(xx), "l"(w67));
        }
        __syncthreads();
    }

    int grow = row0 + r;
    if (grow < n) {
        float dv = g_dinv[grow];
        float f0, f1, f2, f3, f4, f5, f6, f7;
        asm("mov.b64 {%0, %1}, %2;" : "=f"(f0), "=f"(f1) : "l"(acc0));
        asm("mov.b64 {%0, %1}, %2;" : "=f"(f2), "=f"(f3) : "l"(acc1));
        asm("mov.b64 {%0, %1}, %2;" : "=f"(f4), "=f"(f5) : "l"(acc2));
        asm("mov.b64 {%0, %1}, %2;" : "=f"(f6), "=f"(f7) : "l"(acc3));
        float4 o0 = make_float4(f0 * dv, f1 * dv, f2 * dv, f3 * dv);
        float4 o1 = make_float4(f4 * dv, f5 * dv, f6 * dv, f7 * dv);
        float4* dst = reinterpret_cast<float4*>(&g_hp[(long long)grow * F_MID + h * 8]);
        dst[0] = o0;
        dst[1] = o1;
    }
}

// ---------------- layer-1 aggregation: warp per node ------------------------
// h1p = relu(dinv*S + b1) * dinv    (hp -> h1p)
__global__ __launch_bounds__(256) void k_agg1(const float* __restrict__ bias, int n) {
    const int warp = (blockIdx.x * blockDim.x + threadIdx.x) >> 5;
    const int lane = threadIdx.x & 31;
    if (warp >= n) return;
    const int v = warp;
    const int g = lane >> 2;   // edge slot 0..7
    const int c = lane & 3;    // float4 index within 16 features

    const int base = g_rowptr[v];
    const int end  = g_rowptr[v + 1];

    float4 acc = make_float4(0.f, 0.f, 0.f, 0.f);
    #pragma unroll 2
    for (int i = base + g; i < end; i += 8) {
        int s = __ldg(&g_col[i]);
        float4 m = *reinterpret_cast<const float4*>(&g_hp[(long long)s * F_MID + c * 4]);
        acc.x += m.x; acc.y += m.y; acc.z += m.z; acc.w += m.w;
    }
    #pragma unroll
    for (int d = 4; d < 32; d <<= 1) {
        acc.x += __shfl_xor_sync(0xffffffffu, acc.x, d);
        acc.y += __shfl_xor_sync(0xffffffffu, acc.y, d);
        acc.z += __shfl_xor_sync(0xffffffffu, acc.z, d);
        acc.w += __shfl_xor_sync(0xffffffffu, acc.w, d);
    }
    if (lane < 4) {
        float4 self = *reinterpret_cast<const float4*>(&g_hp[(long long)v * F_MID + lane * 4]);
        acc.x += self.x; acc.y += self.y; acc.z += self.z; acc.w += self.w;
        float dv = g_dinv[v];
        float4 bb = *reinterpret_cast<const float4*>(&bias[lane * 4]);
        float4 o;
        o.x = fmaxf(acc.x * dv + bb.x, 0.f) * dv;
        o.y = fmaxf(acc.y * dv + bb.y, 0.f) * dv;
        o.z = fmaxf(acc.z * dv + bb.z, 0.f) * dv;
        o.w = fmaxf(acc.w * dv + bb.w, 0.f) * dv;
        *reinterpret_cast<float4*>(&g_h1p[(long long)v * F_MID + lane * 4]) = o;
    }
}

// ---------------- layer-2 aggregation FUSED with output GEMM + log_softmax --
// s2 = dinv * (sum_{src} h1p[src] + h1p[v]); out = log_softmax(s2 @ W2 + b2)
__global__ __launch_bounds__(256) void k_agg2_out(const float* __restrict__ W2,
                                                 const float* __restrict__ b2,
                                                 float* __restrict__ out, int n) {
    __shared__ float W2s[F_MID * F_OUT];  // 1024 floats
    {
        int tid = threadIdx.x;
        for (int i = tid; i < F_MID * F_OUT; i += 256) W2s[i] = W2[i];
    }
    __syncthreads();

    const int warp = (blockIdx.x * blockDim.x + threadIdx.x) >> 5;
    const int lane = threadIdx.x & 31;
    if (warp >= n) return;
    const int v = warp;
    const int g = lane >> 2;
    const int c = lane & 3;

    const int base = g_rowptr[v];
    const int end  = g_rowptr[v + 1];

    float4 acc = make_float4(0.f, 0.f, 0.f, 0.f);
    #pragma unroll 2
    for (int i = base + g; i < end; i += 8) {
        int s = __ldg(&g_col[i]);
        float4 m = *reinterpret_cast<const float4*>(&g_h1p[(long long)s * F_MID + c * 4]);
        acc.x += m.x; acc.y += m.y; acc.z += m.z; acc.w += m.w;
    }
    #pragma unroll
    for (int d = 4; d < 32; d <<= 1) {
        acc.x += __shfl_xor_sync(0xffffffffu, acc.x, d);
        acc.y += __shfl_xor_sync(0xffffffffu, acc.y, d);
        acc.z += __shfl_xor_sync(0xffffffffu, acc.z, d);
        acc.w += __shfl_xor_sync(0xffffffffu, acc.w, d);
    }
    if (lane < 4) {  // finalize s2 in lanes 0..3 (lane j holds feats 4j..4j+3)
        float4 self = *reinterpret_cast<const float4*>(&g_h1p[(long long)v * F_MID + lane * 4]);
        float dv = g_dinv[v];
        acc.x = (acc.x + self.x) * dv;
        acc.y = (acc.y + self.y) * dv;
        acc.z = (acc.z + self.z) * dv;
        acc.w = (acc.w + self.w) * dv;
    }
    // broadcast the 16 s2 values to all lanes
    float s2[F_MID];
    #pragma unroll
    for (int j = 0; j < 4; j++) {
        s2[4 * j + 0] = __shfl_sync(0xffffffffu, acc.x, j);
        s2[4 * j + 1] = __shfl_sync(0xffffffffu, acc.y, j);
        s2[4 * j + 2] = __shfl_sync(0xffffffffu, acc.z, j);
        s2[4 * j + 3] = __shfl_sync(0xffffffffu, acc.w, j);
    }
    // output GEMM: each lane computes feats (lane) and (lane+32)
    float a = b2[lane];
    float b = b2[lane + 32];
    #pragma unroll
    for (int f = 0; f < F_MID; f++) {
        a = fmaf(s2[f], W2s[f * F_OUT + lane], a);
        b = fmaf(s2[f], W2s[f * F_OUT + lane + 32], b);
    }
    float M = fmaxf(a, b);
    #pragma unroll
    for (int d = 16; d > 0; d >>= 1) M = fmaxf(M, __shfl_xor_sync(0xffffffffu, M, d));
    float sum = expf(a - M) + expf(b - M);
    #pragma unroll
    for (int d = 16; d > 0; d >>= 1) sum += __shfl_xor_sync(0xffffffffu, sum, d);
    float lz = M + logf(sum);
    out[(long long)v * F_OUT + lane]      = a - lz;
    out[(long long)v * F_OUT + lane + 32] = b - lz;
}

// ---------------- launch ----------------------------------------------------
extern "C" void kernel_launch(void* const* d_in, const int* in_sizes, int n_in,
                              void* d_out, int out_size) {
    const float* x  = (const float*)d_in[0];
    const void*  ei = d_in[1];
    const float* W1 = (const float*)d_in[2];
    const float* b1 = (const float*)d_in[3];
    const float* W2 = (const float*)d_in[4];
    const float* b2 = (const float*)d_in[5];
    float*       out = (float*)d_out;

    const int n = in_sizes[0] / F_IN;          // 100000
    const int E = in_sizes[1] / 2;             // 3200000

    const int B = 256;
    const int nodeGrid  = (n + B - 1) / B;
    const int pairGrid  = (E / 2 + B - 1) / B; // 2 edges per thread
    const int tiles     = (n + 1023) / 1024;
    const int warpGrid  = (n + 7) / 8;         // 8 warps per 256-thread block

    k_init_detect<<<nodeGrid, B>>>((const long long*)ei, n);
    k_count<<<pairGrid, B>>>(ei, E);
    k_scanAll<<<tiles, 1024>>>(n);
    k_gemm1<<<(n + 127) / 128, B>>>(x, W1, n);   // launch idx 3 -> profiled
    k_fill<<<pairGrid, B>>>(ei, E);
    k_agg1<<<warpGrid, B>>>(b1, n);
    k_agg2_out<<<warpGrid, B>>>(W2, b2, out, n);
}

// round 9
// speedup vs baseline: 1.2674x; 1.0980x over previous
#include <cuda_runtime.h>
#include <cuda_bf16.h>
#include <math.h>

// ---------------- problem-size constants (fixed per dataset) ----------------
#define NMAX 100000
#define EMAX 3200000
#define F_IN 512
#define F_MID 16
#define F_OUT 64

// ---------------- scratch (static device allocations; no cudaMalloc) -------
__device__ int   g_is64;               // edge_index dtype flag (1 = int64)
__device__ int   g_cnt[NMAX];          // in-degree (excl self loop)
__device__ float g_dinv[NMAX];         // rsqrt(deg+1)
__device__ int   g_tile_pub[128];      // lookback: tile aggregate + 1 (0 = not ready)
__device__ int   g_rowptr[NMAX + 1];
__device__ int   g_cursor[NMAX];
__device__ int   g_col[EMAX];          // CSR source indices grouped by dst
__device__ __align__(16) float g_hp[NMAX * F_MID];    // (x@W1)*dinv
__device__ __align__(16) float g_h1p[NMAX * F_MID];   // relu(layer1)*dinv

// ---------------- init + dtype detection -------------------------------------
// JAX default config demotes int64 -> int32; detect which layout we actually
// got: if the first 16 int64 reads are all valid node ids, it's real int64.
__global__ void k_init_detect(const long long* __restrict__ ei, int n) {
    int i = blockIdx.x * blockDim.x + threadIdx.x;
    if (i < n) g_cnt[i] = 0;
    if (i < 128) g_tile_pub[i] = 0;
    if (i == 0) {
        bool ok64 = true;
        #pragma unroll
        for (int t = 0; t < 16; t++) {
            long long v = ei[t];
            if (v < 0 || v >= NMAX) ok64 = false;
        }
        g_is64 = ok64 ? 1 : 0;
    }
}

// ---------------- degree count (4 edges / thread) ---------------------------
__global__ void k_count(const void* __restrict__ ei, int E) {
    int e4 = (blockIdx.x * blockDim.x + threadIdx.x) * 4;
    if (e4 >= E) return;
    int d[4] = {-1, -1, -1, -1};
    if (e4 + 3 < E) {
        if (g_is64) {
            const long long* p = (const long long*)ei + (long long)E + e4;
            longlong2 v0 = *(const longlong2*)p;
            longlong2 v1 = *(const longlong2*)(p + 2);
            d[0] = (int)v0.x; d[1] = (int)v0.y; d[2] = (int)v1.x; d[3] = (int)v1.y;
        } else {
            int4 v = *(const int4*)((const int*)ei + E + e4);
            d[0] = v.x; d[1] = v.y; d[2] = v.z; d[3] = v.w;
        }
    } else {
        for (int j = 0; j < 4 && e4 + j < E; j++)
            d[j] = g_is64 ? (int)((const long long*)ei)[(long long)E + e4 + j]
                          : ((const int*)ei)[E + e4 + j];
    }
    #pragma unroll
    for (int j = 0; j < 4; j++)
        if ((unsigned)d[j] < NMAX) atomicAdd(&g_cnt[d[j]], 1);
}

// ---------------- single-pass scan with decoupled lookback ------------------
// Builds g_rowptr, g_cursor, g_dinv in one launch. 98 tiles of 1024 all fit in
// wave 1 (<=148 SMs), so spinning on lower-indexed tiles cannot deadlock.
// Publication uses a single word (total+1), so no fence is needed.
__global__ void k_scanAll(int n) {
    __shared__ int wsum[32];
    __shared__ int sprefix;
    const int lane = threadIdx.x & 31;
    const int wid  = threadIdx.x >> 5;
    const int b    = blockIdx.x;
    int idx = b * 1024 + threadIdx.x;
    int v = (idx < n) ? g_cnt[idx] : 0;
    if (idx < n) g_dinv[idx] = rsqrtf((float)(v + 1));  // +1 self loop

    int s = v;
    #pragma unroll
    for (int d = 1; d < 32; d <<= 1) {
        int t = __shfl_up_sync(0xffffffffu, s, d);
        if (lane >= d) s += t;
    }
    if (lane == 31) wsum[wid] = s;
    __syncthreads();
    if (wid == 0) {
        int w = wsum[lane];
        #pragma unroll
        for (int d = 1; d < 32; d <<= 1) {
            int t = __shfl_up_sync(0xffffffffu, w, d);
            if (lane >= d) w += t;
        }
        wsum[lane] = w;  // inclusive over warp sums
    }
    __syncthreads();
    if (wid > 0) s += wsum[wid - 1];
    // s = inclusive prefix within tile; tile total = wsum[31]

    if (threadIdx.x == 0) {
        ((volatile int*)g_tile_pub)[b] = wsum[31] + 1;  // publish aggregate
    }
    // lookback: warp 0 sums aggregates of tiles 0..b-1
    if (wid == 0) {
        int pre = 0;
        for (int j = lane; j < b; j += 32) {
            int p;
            do { p = ((volatile int*)g_tile_pub)[j]; } while (p == 0);
            pre += p - 1;
        }
        #pragma unroll
        for (int d = 16; d > 0; d >>= 1)
            pre += __shfl_xor_sync(0xffffffffu, pre, d);
        if (lane == 0) sprefix = pre;
    }
    __syncthreads();
    int excl = sprefix + s - v;
    if (idx < n) {
        g_rowptr[idx] = excl;
        g_cursor[idx] = excl;
        if (idx == n - 1) g_rowptr[n] = sprefix + s;
    }
}

// ---------------- CSR bucket fill (4 edges / thread) -------------------------
__global__ void k_fill(const void* __restrict__ ei, int E) {
    int e4 = (blockIdx.x * blockDim.x + threadIdx.x) * 4;
    if (e4 >= E) return;
    int s[4] = {-1, -1, -1, -1}, d[4] = {-1, -1, -1, -1};
    if (e4 + 3 < E) {
        if (g_is64) {
            const long long* ps = (const long long*)ei + e4;
            const long long* pd = (const long long*)ei + (long long)E + e4;
            longlong2 a0 = *(const longlong2*)ps;
            longlong2 a1 = *(const longlong2*)(ps + 2);
            longlong2 b0 = *(const longlong2*)pd;
            longlong2 b1 = *(const longlong2*)(pd + 2);
            s[0] = (int)a0.x; s[1] = (int)a0.y; s[2] = (int)a1.x; s[3] = (int)a1.y;
            d[0] = (int)b0.x; d[1] = (int)b0.y; d[2] = (int)b1.x; d[3] = (int)b1.y;
        } else {
            int4 vs = *(const int4*)((const int*)ei + e4);
            int4 vd = *(const int4*)((const int*)ei + E + e4);
            s[0] = vs.x; s[1] = vs.y; s[2] = vs.z; s[3] = vs.w;
            d[0] = vd.x; d[1] = vd.y; d[2] = vd.z; d[3] = vd.w;
        }
    } else {
        for (int j = 0; j < 4 && e4 + j < E; j++) {
            if (g_is64) {
                s[j] = (int)((const long long*)ei)[e4 + j];
                d[j] = (int)((const long long*)ei)[(long long)E + e4 + j];
            } else {
                s[j] = ((const int*)ei)[e4 + j];
                d[j] = ((const int*)ei)[E + e4 + j];
            }
        }
    }
    #pragma unroll
    for (int j = 0; j < 4; j++) {
        if ((unsigned)s[j] < NMAX && (unsigned)d[j] < NMAX) {
            int pos = atomicAdd(&g_cursor[d[j]], 1);
            g_col[pos] = s[j];
        }
    }
}

// ---------------- GEMM1: hp = (x @ W1) * dinv[row]  (100000x512 @ 512x16) ---
// v3: 2 rows/thread (256-row tile) so each weight load feeds 8 FFMA2, and x
// read from smem as float4 (4 k per LDS.128). f32x2 packed FMAs throughout.
__global__ __launch_bounds__(256) void k_gemm1(const float* __restrict__ x,
                                               const float* __restrict__ W1,
                                               int n) {
    __shared__ __align__(16) float Xs[256][36];   // 36KB; pad 36 keeps 16B align
    __shared__ __align__(16) float Ws[32][16];    // 2KB K-chunk of W1
    const int tid = threadIdx.x;
    const int row0 = blockIdx.x * 256;
    const int r = tid >> 1;        // 0..127
    const int h = tid & 1;         // output half: 8 features each
    const int rA = r, rB = r + 128;

    unsigned long long a0 = 0ull, a1 = 0ull, a2 = 0ull, a3 = 0ull;  // row A
    unsigned long long b0 = 0ull, b1 = 0ull, b2 = 0ull, b3 = 0ull;  // row B

    unsigned int ws_base =
        (unsigned int)__cvta_generic_to_shared(&Ws[0][0]) + (unsigned int)(h * 32);

    for (int k0 = 0; k0 < F_IN; k0 += 32) {
        // stage X tile: 256 rows x 32 k = 2048 float4, 8 per thread
        #pragma unroll
        for (int j = 0; j < 8; j++) {
            int lin = tid + 256 * j;            // 0..2047
            int rr = lin >> 3;                  // 0..255
            int cc = (lin & 7) << 2;            // 0,4,...,28
            int grow = row0 + rr;
            float4 v = make_float4(0.f, 0.f, 0.f, 0.f);
            if (grow < n)
                v = *reinterpret_cast<const float4*>(&x[(long long)grow * F_IN + k0 + cc]);
            *reinterpret_cast<float4*>(&Xs[rr][cc]) = v;
        }
        // stage W chunk: 32x16 = 512 floats = 128 float4
        if (tid < 128)
            reinterpret_cast<float4*>(Ws)[tid] =
                reinterpret_cast<const float4*>(W1 + k0 * F_MID)[tid];
        __syncthreads();

        #pragma unroll
        for (int kk = 0; kk < 32; kk += 4) {
            float4 xa = *reinterpret_cast<const float4*>(&Xs[rA][kk]);
            float4 xb = *reinterpret_cast<const float4*>(&Xs[rB][kk]);
            const float xav[4] = {xa.x, xa.y, xa.z, xa.w};
            const float xbv[4] = {xb.x, xb.y, xb.z, xb.w};
            #pragma unroll
            for (int j = 0; j < 4; j++) {
                unsigned long long xxa, xxb, w01, w23, w45, w67;
                asm("mov.b64 %0, {%1, %1};" : "=l"(xxa) : "f"(xav[j]));
                asm("mov.b64 %0, {%1, %1};" : "=l"(xxb) : "f"(xbv[j]));
                unsigned int adr = ws_base + (unsigned int)((kk + j) * 64);
                asm("ld.shared.v2.b64 {%0, %1}, [%2];"
                    : "=l"(w01), "=l"(w23) : "r"(adr));
                asm("ld.shared.v2.b64 {%0, %1}, [%2];"
                    : "=l"(w45), "=l"(w67) : "r"(adr + 16));
                asm("fma.rn.f32x2 %0, %1, %2, %0;" : "+l"(a0) : "l"(xxa), "l"(w01));
                asm("fma.rn.f32x2 %0, %1, %2, %0;" : "+l"(a1) : "l"(xxa), "l"(w23));
                asm("fma.rn.f32x2 %0, %1, %2, %0;" : "+l"(a2) : "l"(xxa), "l"(w45));
                asm("fma.rn.f32x2 %0, %1, %2, %0;" : "+l"(a3) : "l"(xxa), "l"(w67));
                asm("fma.rn.f32x2 %0, %1, %2, %0;" : "+l"(b0) : "l"(xxb), "l"(w01));
                asm("fma.rn.f32x2 %0, %1, %2, %0;" : "+l"(b1) : "l"(xxb), "l"(w23));
                asm("fma.rn.f32x2 %0, %1, %2, %0;" : "+l"(b2) : "l"(xxb), "l"(w45));
                asm("fma.rn.f32x2 %0, %1, %2, %0;" : "+l"(b3) : "l"(xxb), "l"(w67));
            }
        }
        __syncthreads();
    }

    #pragma unroll
    for (int rowSel = 0; rowSel < 2; rowSel++) {
        int grow = row0 + (rowSel ? rB : rA);
        if (grow < n) {
            unsigned long long c0 = rowSel ? b0 : a0;
            unsigned long long c1 = rowSel ? b1 : a1;
            unsigned long long c2 = rowSel ? b2 : a2;
            unsigned long long c3 = rowSel ? b3 : a3;
            float dv = g_dinv[grow];
            float f0, f1, f2, f3, f4, f5, f6, f7;
            asm("mov.b64 {%0, %1}, %2;" : "=f"(f0), "=f"(f1) : "l"(c0));
            asm("mov.b64 {%0, %1}, %2;" : "=f"(f2), "=f"(f3) : "l"(c1));
            asm("mov.b64 {%0, %1}, %2;" : "=f"(f4), "=f"(f5) : "l"(c2));
            asm("mov.b64 {%0, %1}, %2;" : "=f"(f6), "=f"(f7) : "l"(c3));
            float4* dst = reinterpret_cast<float4*>(&g_hp[(long long)grow * F_MID + h * 8]);
            dst[0] = make_float4(f0 * dv, f1 * dv, f2 * dv, f3 * dv);
            dst[1] = make_float4(f4 * dv, f5 * dv, f6 * dv, f7 * dv);
        }
    }
}

// ---------------- layer-1 aggregation: warp per node ------------------------
// h1p = relu(dinv*S + b1) * dinv    (hp -> h1p)
__global__ __launch_bounds__(256) void k_agg1(const float* __restrict__ bias, int n) {
    const int warp = (blockIdx.x * blockDim.x + threadIdx.x) >> 5;
    const int lane = threadIdx.x & 31;
    if (warp >= n) return;
    const int v = warp;
    const int g = lane >> 2;   // edge slot 0..7
    const int c = lane & 3;    // float4 index within 16 features

    const int base = g_rowptr[v];
    const int end  = g_rowptr[v + 1];

    float4 acc = make_float4(0.f, 0.f, 0.f, 0.f);
    #pragma unroll 2
    for (int i = base + g; i < end; i += 8) {
        int s = __ldg(&g_col[i]);
        float4 m = *reinterpret_cast<const float4*>(&g_hp[(long long)s * F_MID + c * 4]);
        acc.x += m.x; acc.y += m.y; acc.z += m.z; acc.w += m.w;
    }
    #pragma unroll
    for (int d = 4; d < 32; d <<= 1) {
        acc.x += __shfl_xor_sync(0xffffffffu, acc.x, d);
        acc.y += __shfl_xor_sync(0xffffffffu, acc.y, d);
        acc.z += __shfl_xor_sync(0xffffffffu, acc.z, d);
        acc.w += __shfl_xor_sync(0xffffffffu, acc.w, d);
    }
    if (lane < 4) {
        float4 self = *reinterpret_cast<const float4*>(&g_hp[(long long)v * F_MID + lane * 4]);
        acc.x += self.x; acc.y += self.y; acc.z += self.z; acc.w += self.w;
        float dv = g_dinv[v];
        float4 bb = *reinterpret_cast<const float4*>(&bias[lane * 4]);
        float4 o;
        o.x = fmaxf(acc.x * dv + bb.x, 0.f) * dv;
        o.y = fmaxf(acc.y * dv + bb.y, 0.f) * dv;
        o.z = fmaxf(acc.z * dv + bb.z, 0.f) * dv;
        o.w = fmaxf(acc.w * dv + bb.w, 0.f) * dv;
        *reinterpret_cast<float4*>(&g_h1p[(long long)v * F_MID + lane * 4]) = o;
    }
}

// ---------------- layer-2 aggregation FUSED with output GEMM + log_softmax --
// s2 = dinv * (sum_{src} h1p[src] + h1p[v]); out = log_softmax(s2 @ W2 + b2)
__global__ __launch_bounds__(256) void k_agg2_out(const float* __restrict__ W2,
                                                 const float* __restrict__ b2,
                                                 float* __restrict__ out, int n) {
    __shared__ float W2s[F_MID * F_OUT];  // 1024 floats
    {
        int tid = threadIdx.x;
        for (int i = tid; i < F_MID * F_OUT; i += 256) W2s[i] = W2[i];
    }
    __syncthreads();

    const int warp = (blockIdx.x * blockDim.x + threadIdx.x) >> 5;
    const int lane = threadIdx.x & 31;
    if (warp >= n) return;
    const int v = warp;
    const int g = lane >> 2;
    const int c = lane & 3;

    const int base = g_rowptr[v];
    const int end  = g_rowptr[v + 1];

    float4 acc = make_float4(0.f, 0.f, 0.f, 0.f);
    #pragma unroll 2
    for (int i = base + g; i < end; i += 8) {
        int s = __ldg(&g_col[i]);
        float4 m = *reinterpret_cast<const float4*>(&g_h1p[(long long)s * F_MID + c * 4]);
        acc.x += m.x; acc.y += m.y; acc.z += m.z; acc.w += m.w;
    }
    #pragma unroll
    for (int d = 4; d < 32; d <<= 1) {
        acc.x += __shfl_xor_sync(0xffffffffu, acc.x, d);
        acc.y += __shfl_xor_sync(0xffffffffu, acc.y, d);
        acc.z += __shfl_xor_sync(0xffffffffu, acc.z, d);
        acc.w += __shfl_xor_sync(0xffffffffu, acc.w, d);
    }
    if (lane < 4) {  // finalize s2 in lanes 0..3 (lane j holds feats 4j..4j+3)
        float4 self = *reinterpret_cast<const float4*>(&g_h1p[(long long)v * F_MID + lane * 4]);
        float dv = g_dinv[v];
        acc.x = (acc.x + self.x) * dv;
        acc.y = (acc.y + self.y) * dv;
        acc.z = (acc.z + self.z) * dv;
        acc.w = (acc.w + self.w) * dv;
    }
    // broadcast the 16 s2 values to all lanes
    float s2[F_MID];
    #pragma unroll
    for (int j = 0; j < 4; j++) {
        s2[4 * j + 0] = __shfl_sync(0xffffffffu, acc.x, j);
        s2[4 * j + 1] = __shfl_sync(0xffffffffu, acc.y, j);
        s2[4 * j + 2] = __shfl_sync(0xffffffffu, acc.z, j);
        s2[4 * j + 3] = __shfl_sync(0xffffffffu, acc.w, j);
    }
    // output GEMM: each lane computes feats (lane) and (lane+32)
    float a = b2[lane];
    float b = b2[lane + 32];
    #pragma unroll
    for (int f = 0; f < F_MID; f++) {
        a = fmaf(s2[f], W2s[f * F_OUT + lane], a);
        b = fmaf(s2[f], W2s[f * F_OUT + lane + 32], b);
    }
    float M = fmaxf(a, b);
    #pragma unroll
    for (int d = 16; d > 0; d >>= 1) M = fmaxf(M, __shfl_xor_sync(0xffffffffu, M, d));
    float sum = expf(a - M) + expf(b - M);
    #pragma unroll
    for (int d = 16; d > 0; d >>= 1) sum += __shfl_xor_sync(0xffffffffu, sum, d);
    float lz = M + logf(sum);
    out[(long long)v * F_OUT + lane]      = a - lz;
    out[(long long)v * F_OUT + lane + 32] = b - lz;
}

// ---------------- launch ----------------------------------------------------
extern "C" void kernel_launch(void* const* d_in, const int* in_sizes, int n_in,
                              void* d_out, int out_size) {
    const float* x  = (const float*)d_in[0];
    const void*  ei = d_in[1];
    const float* W1 = (const float*)d_in[2];
    const float* b1 = (const float*)d_in[3];
    const float* W2 = (const float*)d_in[4];
    const float* b2 = (const float*)d_in[5];
    float*       out = (float*)d_out;

    const int n = in_sizes[0] / F_IN;          // 100000
    const int E = in_sizes[1] / 2;             // 3200000

    const int B = 256;
    const int nodeGrid  = (n + B - 1) / B;
    const int quadGrid  = (E / 4 + B - 1) / B; // 4 edges per thread
    const int tiles     = (n + 1023) / 1024;
    const int warpGrid  = (n + 7) / 8;         // 8 warps per 256-thread block

    k_init_detect<<<nodeGrid, B>>>((const long long*)ei, n);
    k_count<<<quadGrid, B>>>(ei, E);
    k_scanAll<<<tiles, 1024>>>(n);
    k_gemm1<<<(n + 255) / 256, B>>>(x, W1, n);   // launch idx 3 -> profiled
    k_fill<<<quadGrid, B>>>(ei, E);
    k_agg1<<<warpGrid, B>>>(b1, n);
    k_agg2_out<<<warpGrid, B>>>(W2, b2, out, n);
}